// round 13
// baseline (speedup 1.0000x reference)
#include <cuda_runtime.h>
#include <math.h>

#define NB 256        // batch
#define NT 64         // timesteps
#define NACT 6
#define GDIM 3072
#define ZA_LD 1040    // 1024 z + 6 act + 10 zero pad (K=1040 multiple of 16)
#define WI1_K 1040

// ---------------- scratch (device globals: no allocation allowed) ----------------
__device__ float g_ZA[NB * ZA_LD];        // [z (1024) | action (6) | zero pad]
__device__ float g_H1[NB * 1024];         // imagine hidden (post-silu)
__device__ float g_IB[NB * 2048];         // [inp (1024) | belief (1024)]
__device__ float g_HP[NB * 1024];         // prior hidden (post-silu)
__device__ float g_HO[NB * 1024];         // post hidden (post-silu)
__device__ float g_PP[8][NB * 1024];      // split-K partial pool (reused per phase)
__device__ float g_GG[4][NB * GDIM];      // gg GEMM partials
__device__ float g_Wi1p[WI1_K * 1024];    // Wi1 zero-padded to K=1040 rows

// ---------------- helpers ----------------
__device__ __forceinline__ float warp_sum(float v) {
#pragma unroll
    for (int o = 16; o; o >>= 1) v += __shfl_xor_sync(0xffffffffu, v, o);
    return v;
}
__device__ __forceinline__ float warp_max(float v) {
#pragma unroll
    for (int o = 16; o; o >>= 1) v = fmaxf(v, __shfl_xor_sync(0xffffffffu, v, o));
    return v;
}
__device__ __forceinline__ float silu_f(float x) {
    double e = exp(-(double)x);
    return (float)((double)x / (1.0 + e));
}
__device__ __forceinline__ float sigmoid_f(float x) {
    return (float)(1.0 / (1.0 + exp(-(double)x)));
}

// ---------------- packed f32x2 via PTX (per-lane identical to FFMA rounding) ----
__device__ __forceinline__ double dup2(float x) {
    double r; asm("mov.b64 %0, {%1,%1};" : "=d"(r) : "f"(x)); return r;
}
__device__ __forceinline__ double ffma2(double a, double b, double c) {
    double d; asm("fma.rn.f32x2 %0, %1, %2, %3;" : "=d"(d) : "d"(a), "d"(b), "d"(c)); return d;
}
__device__ __forceinline__ float2 unpack2(double p) {
    float2 f; asm("mov.b64 {%0,%1}, %2;" : "=f"(f.x), "=f"(f.y) : "d"(p)); return f;
}

__device__ __forceinline__ void cp16(void* smem, const void* g) {
    unsigned s = (unsigned)__cvta_generic_to_shared(smem);
    asm volatile("cp.async.ca.shared.global [%0], [%1], 16;\n" :: "r"(s), "l"(g));
}
__device__ __forceinline__ void cp_commit() { asm volatile("cp.async.commit_group;\n"); }
__device__ __forceinline__ void cp_wait0()  { asm volatile("cp.async.wait_group 0;\n"); }

// ---------------- init ----------------
__global__ void init_kernel(const float* __restrict__ z0, const float* __restrict__ b0,
                            const float* __restrict__ actions0) {
    int i = blockIdx.x * blockDim.x + threadIdx.x;
    if (i < NB * 1024) {
        int r = i >> 10, c = i & 1023;
        g_ZA[r * ZA_LD + c] = z0[i];
        g_IB[r * 2048 + 1024 + c] = b0[i];
        if (c >= 1024 - 10) g_ZA[r * ZA_LD + (c + 16)] = 0.0f;  // cols 1030..1039
        if (c < NACT) g_ZA[r * ZA_LD + 1024 + c] = actions0[r * NACT + c];
    }
}
__global__ void padw_kernel(const float* __restrict__ Wi1) {
    int i = blockIdx.x * blockDim.x + threadIdx.x;
    if (i < WI1_K * 1024) {
        int r = i >> 10;
        g_Wi1p[i] = (r < 1030) ? Wi1[i] : 0.0f;
    }
}

// ---------------- GEMM problem descriptor: z-slice -> k-range ----------------
// slice s = blockIdx.z - zlo; k0(s) = (s==0) ? 0 : kfe + (s-1)*kstep;
// k1(s) = kfe + s*kstep; partial out = C + s*cstride.
struct GP {
    const float* A;   int lda;    // k in [0, ksplit)
    const float* A2;  int lda2;   // k in [ksplit, K)
    int ksplit;
    const float* W;   int ldw;
    float* C;         int ldc;
    long long cstride;            // elements between split partial buffers
    int zlo;                      // first z owned by this problem
    int kfe;                      // end of first slice
    int kstep;                    // size of subsequent slices
};

// C_partial = A[k0:k1] @ W[k0:k1]. BM=BN=64, BK=16, 256 threads, 4x4 microtile
// computed as 4x(2-pair) FFMA2. A tile stored in smem PRE-DUPLICATED as doubles
// (dup cost amortized into the tile store). Per kk: 2 LDS.128 (A) + 1 LDS.128 (B)
// + 8 FFMA2. Per-output accumulation is ascending-k fma.rn per lane -> bit-
// identical to the scalar version. Double-buffered, cp.async for W.
__global__ void __launch_bounds__(256) gemm11_kernel(GP p0, GP p1) {
    GP p = (blockIdx.z >= (unsigned)p1.zlo) ? p1 : p0;
    const int s = blockIdx.z - p.zlo;
    const int k0 = (s == 0) ? 0 : p.kfe + (s - 1) * p.kstep;
    const int k1 = p.kfe + s * p.kstep;
    float* Cout = p.C + (long long)s * p.cstride;

    __shared__ double As2[2][16][64];   // [buf][k][m] pre-duplicated pairs (16 KB)
    __shared__ float  Bs [2][16][64];   // [buf][k][n] (8 KB)

    const int tid = threadIdx.x;
    const int m0 = blockIdx.y * 64, n0 = blockIdx.x * 64;
    const int ar = tid & 63, ac = (tid >> 6) << 2;     // A loader: row ar, k-cols ac..ac+3
    const int br = tid >> 4, bc = (tid & 15) << 2;     // W loader: k-row br, n-cols bc..bc+3
    const int ty = tid >> 4, tx = tid & 15;

    const int t0 = k0 >> 4, tN = k1 >> 4;

    auto aptr = [&](int t) -> const float* {
        int kb = t << 4;
        return (kb < p.ksplit)
            ? p.A  + (size_t)(m0 + ar) * p.lda  + kb + ac
            : p.A2 + (size_t)(m0 + ar) * p.lda2 + (kb - p.ksplit) + ac;
    };

    double acc[4][2];
#pragma unroll
    for (int i = 0; i < 4; i++) { acc[i][0] = dup2(0.0f); acc[i][1] = dup2(0.0f); }

    // prologue: fill buffer 0
    {
        float4 a = *(const float4*)aptr(t0);
        cp16(&Bs[0][br][bc], p.W + (size_t)(k0 + br) * p.ldw + n0 + bc);
        cp_commit();
        As2[0][ac + 0][ar] = dup2(a.x); As2[0][ac + 1][ar] = dup2(a.y);
        As2[0][ac + 2][ar] = dup2(a.z); As2[0][ac + 3][ar] = dup2(a.w);
        cp_wait0();
    }
    __syncthreads();

    for (int t = t0; t < tN; t++) {
        const int cur = (t - t0) & 1, nxt = cur ^ 1;
        const bool more = (t + 1) < tN;
        float4 apf;
        if (more) {
            apf = *(const float4*)aptr(t + 1);
            cp16(&Bs[nxt][br][bc], p.W + (size_t)((t + 1) * 16 + br) * p.ldw + n0 + bc);
            cp_commit();
        }
#pragma unroll
        for (int kk = 0; kk < 16; kk++) {
            double2 a01 = *(const double2*)&As2[cur][kk][ty * 4];
            double2 a23 = *(const double2*)&As2[cur][kk][ty * 4 + 2];
            double2 b   = *(const double2*)&Bs[cur][kk][tx * 4];
            acc[0][0] = ffma2(a01.x, b.x, acc[0][0]); acc[0][1] = ffma2(a01.x, b.y, acc[0][1]);
            acc[1][0] = ffma2(a01.y, b.x, acc[1][0]); acc[1][1] = ffma2(a01.y, b.y, acc[1][1]);
            acc[2][0] = ffma2(a23.x, b.x, acc[2][0]); acc[2][1] = ffma2(a23.x, b.y, acc[2][1]);
            acc[3][0] = ffma2(a23.y, b.x, acc[3][0]); acc[3][1] = ffma2(a23.y, b.y, acc[3][1]);
        }
        if (more) {
            As2[nxt][ac + 0][ar] = dup2(apf.x); As2[nxt][ac + 1][ar] = dup2(apf.y);
            As2[nxt][ac + 2][ar] = dup2(apf.z); As2[nxt][ac + 3][ar] = dup2(apf.w);
            cp_wait0();
        }
        __syncthreads();
    }

#pragma unroll
    for (int i = 0; i < 4; i++) {
        const int m = m0 + ty * 4 + i;
        float2 lo = unpack2(acc[i][0]);
        float2 hi = unpack2(acc[i][1]);
        float4 o = make_float4(lo.x, lo.y, hi.x, hi.y);
        *(float4*)(Cout + (size_t)m * p.ldc + n0 + tx * 4) = o;
    }
}

// ---------------- fuse8: out = [silu](sum PP[0..7] + bias) ----------------------
// grid: 256 blocks x 256 threads x float4 = 262144 floats
__global__ void fuse8_kernel(const float* __restrict__ bias, float* __restrict__ out,
                             int ldo, int dsilu) {
    int i = (blockIdx.x * blockDim.x + threadIdx.x) << 2;
    int r = i >> 10, c = i & 1023;
    float4 o = *(const float4*)&g_PP[0][i];
#pragma unroll
    for (int s = 1; s < 8; s++) {
        float4 v = *(const float4*)&g_PP[s][i];
        o.x += v.x; o.y += v.y; o.z += v.z; o.w += v.w;
    }
    float4 b4 = *(const float4*)&bias[c];
    o.x += b4.x; o.y += b4.y; o.z += b4.z; o.w += b4.w;
    if (dsilu) { o.x = silu_f(o.x); o.y = silu_f(o.y); o.z = silu_f(o.z); o.w = silu_f(o.w); }
    *(float4*)(out + (size_t)r * ldo + c) = o;
}

// ---------------- fuse44: HP = silu(PP[0..3]+bp1), HO = silu(PP[4..7]+bo1) -------
__global__ void fuse44_kernel(const float* __restrict__ bp1, const float* __restrict__ bo1) {
    int i = (blockIdx.x * blockDim.x + threadIdx.x) << 2;
    int c = i & 1023;
    const int base = blockIdx.y * 4;
    const float* bias = blockIdx.y ? bo1 : bp1;
    float* out = blockIdx.y ? g_HO : g_HP;
    float4 o = *(const float4*)&g_PP[base][i];
#pragma unroll
    for (int s = 1; s < 4; s++) {
        float4 v = *(const float4*)&g_PP[base + s][i];
        o.x += v.x; o.y += v.y; o.z += v.z; o.w += v.w;
    }
    float4 b4 = *(const float4*)&bias[c];
    o.x = silu_f(o.x + b4.x);
    o.y = silu_f(o.y + b4.y);
    o.z = silu_f(o.z + b4.z);
    o.w = silu_f(o.w + b4.w);
    *(float4*)(out + i) = o;
}

// ---------------- LayerNorm(3072, eps=1e-3) + GRU update (sums 4 GG partials) ----
__global__ void lngru_kernel(const float* __restrict__ ln_scale, const float* __restrict__ ln_bias) {
    const int row = blockIdx.x;
    const int tid = threadIdx.x;
    __shared__ float sh[8];
    __shared__ float bcast;

    const float* g0 = g_GG[0] + (size_t)row * GDIM;
    const float* g1 = g_GG[1] + (size_t)row * GDIM;
    const float* g2 = g_GG[2] + (size_t)row * GDIM;
    const float* g3 = g_GG[3] + (size_t)row * GDIM;
    float x[12];
    float s = 0.0f;
#pragma unroll
    for (int i = 0; i < 12; i++) {
        int j = tid + i * 256;
        x[i] = ((g0[j] + g1[j]) + (g2[j] + g3[j]));
        s += x[i];
    }

    s = warp_sum(s);
    if ((tid & 31) == 0) sh[tid >> 5] = s;
    __syncthreads();
    if (tid < 32) {
        float t = (tid < 8) ? sh[tid] : 0.0f;
        t = warp_sum(t);
        if (tid == 0) bcast = t;
    }
    __syncthreads();
    const float mu = __fdiv_rn(bcast, 3072.0f);
    __syncthreads();

    float v = 0.0f;
#pragma unroll
    for (int i = 0; i < 12; i++) { float d = x[i] - mu; v += d * d; }
    v = warp_sum(v);
    if ((tid & 31) == 0) sh[tid >> 5] = v;
    __syncthreads();
    if (tid < 32) {
        float t = (tid < 8) ? sh[tid] : 0.0f;
        t = warp_sum(t);
        if (tid == 0) bcast = t;
    }
    __syncthreads();
    const float var = __fdiv_rn(bcast, 3072.0f);
    const float denom = __fsqrt_rn(var + 1e-3f);

#pragma unroll
    for (int jj = 0; jj < 4; jj++) {
        int j = tid + jj * 256;
        float yr = __fdiv_rn(x[jj]     - mu, denom) * ln_scale[j]        + ln_bias[j];
        float yc = __fdiv_rn(x[jj + 4] - mu, denom) * ln_scale[j + 1024] + ln_bias[j + 1024];
        float yu = __fdiv_rn(x[jj + 8] - mu, denom) * ln_scale[j + 2048] + ln_bias[j + 2048];
        float reset = sigmoid_f(yr);
        float cand  = (float)tanh((double)(reset * yc));
        float upd   = sigmoid_f(yu - 1.0f);   // UPDATE_BIAS = -1
        float bprev = g_IB[(size_t)row * 2048 + 1024 + j];
        float bn = upd * cand + (1.0f - upd) * bprev;
        g_IB[(size_t)row * 2048 + 1024 + j] = bn;
    }
}

// ---------------- softmax/unimix/KL + gumbel sample (sums 4+4 logit partials) ----
__global__ void sample_kernel(const float* __restrict__ U_t, float* __restrict__ losses_t,
                              const float* __restrict__ bp2, const float* __restrict__ bo2,
                              const float* __restrict__ actions_next) {
    const int row = blockIdx.x;
    const int tid = threadIdx.x;
    const int warp = tid >> 5, lane = tid & 31;
    __shared__ float klsh[8];

    if (actions_next && tid < NACT)
        g_ZA[(size_t)row * ZA_LD + 1024 + tid] = actions_next[row * NACT + tid];

    float klacc = 0.0f;
#pragma unroll
    for (int sg = 0; sg < 4; sg++) {
        const int s2 = warp * 4 + sg;
        const int col = s2 * 32 + lane;
        const int idx = row * 1024 + col;

        float pl = ((g_PP[0][idx] + g_PP[1][idx]) + (g_PP[2][idx] + g_PP[3][idx])) + bp2[col];
        float ql = ((g_PP[4][idx] + g_PP[5][idx]) + (g_PP[6][idx] + g_PP[7][idx])) + bo2[col];
        pl = fminf(fmaxf(pl, -20.0f), 20.0f);
        ql = fminf(fmaxf(ql, -20.0f), 20.0f);

        float pm = warp_max(pl);
        float pe = (float)exp((double)(pl - pm));
        float ps = warp_sum(pe);
        float pp = __fdiv_rn(pe, ps) * 0.99f + (0.01f / 32.0f);

        float qm = warp_max(ql);
        float qe = (float)exp((double)(ql - qm));
        float qs = warp_sum(qe);
        float qp = __fdiv_rn(qe, qs) * 0.99f + (0.01f / 32.0f);

        klacc += qp * (float)(log((double)(qp + 1e-8f)) - log((double)(pp + 1e-8f)));

        float u = U_t[idx];
        float gum = (float)(-log(-log((double)u + 1e-6) + 1e-6));
        float val = (float)log((double)fmaxf(qp, 1e-6f)) + gum;
        float bv = val; int bi = lane;
#pragma unroll
        for (int o = 16; o; o >>= 1) {
            float ov = __shfl_xor_sync(0xffffffffu, bv, o);
            int   oi = __shfl_xor_sync(0xffffffffu, bi, o);
            if (ov > bv || (ov == bv && oi < bi)) { bv = ov; bi = oi; }
        }
        float y = (lane == bi) ? 1.0f : 0.0f;
        float z = __fsub_rn(__fadd_rn(y, qp), qp);
        g_ZA[(size_t)row * ZA_LD + col] = z;
    }

    float w = warp_sum(klacc);
    if (lane == 0) klsh[warp] = w;
    __syncthreads();
    if (tid == 0) {
        float kl = 0.0f;
#pragma unroll
        for (int i = 0; i < 8; i++) kl += klsh[i];
        float m = fmaxf(kl, 0.1f);
        losses_t[row] = 1.0f * m + 0.1f * m;
    }
}

// ---------------- launch ----------------
extern "C" void kernel_launch(void* const* d_in, const int* in_sizes, int n_in,
                              void* d_out, int out_size) {
    const float* b0       = (const float*)d_in[0];
    const float* z0       = (const float*)d_in[1];
    const float* actions  = (const float*)d_in[2];
    const float* obs      = (const float*)d_in[3];
    const float* u_noise  = (const float*)d_in[4];
    const float* Wi1      = (const float*)d_in[5];
    const float* bi1      = (const float*)d_in[6];
    const float* Wi2      = (const float*)d_in[7];
    const float* bi2      = (const float*)d_in[8];
    const float* Wg       = (const float*)d_in[9];
    const float* ln_scale = (const float*)d_in[10];
    const float* ln_bias  = (const float*)d_in[11];
    const float* Wo1      = (const float*)d_in[12];
    const float* bo1      = (const float*)d_in[13];
    const float* Wo2      = (const float*)d_in[14];
    const float* bo2      = (const float*)d_in[15];
    const float* Wp1      = (const float*)d_in[16];
    const float* bp1      = (const float*)d_in[17];
    const float* Wp2      = (const float*)d_in[18];
    const float* bp2      = (const float*)d_in[19];
    float* out = (float*)d_out;

    float *pZA, *pH1, *pIB, *pHP, *pHO, *pWi1p, *pPP, *pGG;
    cudaGetSymbolAddress((void**)&pZA, g_ZA);
    cudaGetSymbolAddress((void**)&pH1, g_H1);
    cudaGetSymbolAddress((void**)&pIB, g_IB);
    cudaGetSymbolAddress((void**)&pHP, g_HP);
    cudaGetSymbolAddress((void**)&pHO, g_HO);
    cudaGetSymbolAddress((void**)&pWi1p, g_Wi1p);
    cudaGetSymbolAddress((void**)&pPP, g_PP);
    cudaGetSymbolAddress((void**)&pGG, g_GG);

    const long long PSTRIDE = (long long)NB * 1024;
    const long long GSTRIDE = (long long)NB * GDIM;
    const float* belief = pIB + 1024;

    init_kernel<<<(NB * 1024 + 255) / 256, 256>>>(z0, b0, actions);
    padw_kernel<<<(WI1_K * 1024 + 255) / 256, 256>>>(Wi1);

    const dim3 gS8(16, 4, 8);   // N=1024, 8 slices total: 512 blocks
    const dim3 gG4(48, 4, 4);   // N=3072, split-4: 768 blocks
    const dim3 gF(256, 1, 1);
    const dim3 gF2(256, 2, 1);

    for (int t = 0; t < NT; t++) {
        const float* obs_t = obs + (size_t)t * NB * 1024;

        // ---- imagine layer 1: ZA @ Wi1p, K=1040, split-8 (144 + 7x128) ----
        {
            GP a{pZA, ZA_LD, pZA, ZA_LD, WI1_K, pWi1p, 1024, pPP, 1024, PSTRIDE, 0, 144, 128};
            gemm11_kernel<<<gS8, 256>>>(a, a);
        }
        fuse8_kernel<<<gF, 256>>>(bi1, pH1, 1024, 1);

        // ---- imagine layer 2: H1 @ Wi2, K=1024, split-8 ----
        {
            GP a{pH1, 1024, pH1, 1024, 1024, Wi2, 1024, pPP, 1024, PSTRIDE, 0, 128, 128};
            gemm11_kernel<<<gS8, 256>>>(a, a);
        }
        fuse8_kernel<<<gF, 256>>>(bi2, pIB, 2048, 0);

        // ---- GRU gates: IB @ Wg, K=2048, N=3072, split-4 ----
        {
            GP a{pIB, 2048, pIB, 2048, 2048, Wg, 3072, pGG, 3072, GSTRIDE, 0, 512, 512};
            gemm11_kernel<<<gG4, 256>>>(a, a);
        }
        lngru_kernel<<<NB, 256>>>(ln_scale, ln_bias);

        // ---- prior L1 split-4 (z 0..3) || posterior L1 split-4 (z 4..7) ----
        {
            GP a{belief, 2048, belief, 2048, 1024, Wp1, 1024, pPP, 1024, PSTRIDE, 0, 256, 256};
            GP b{obs_t,  1024, belief, 2048, 1024, Wo1, 1024, pPP + 4 * PSTRIDE, 1024, PSTRIDE, 4, 512, 512};
            gemm11_kernel<<<gS8, 256>>>(a, b);
        }
        fuse44_kernel<<<gF2, 256>>>(bp1, bo1);

        // ---- prior L2 split-4 || posterior L2 split-4 ----
        {
            GP a{pHP, 1024, pHP, 1024, 1024, Wp2, 1024, pPP, 1024, PSTRIDE, 0, 256, 256};
            GP b{pHO, 1024, pHO, 1024, 1024, Wo2, 1024, pPP + 4 * PSTRIDE, 1024, PSTRIDE, 4, 256, 256};
            gemm11_kernel<<<gS8, 256>>>(a, b);
        }

        // ---- probs + KL + gumbel sample (+ stage next actions) ----
        const float* an = (t + 1 < NT) ? (actions + (size_t)(t + 1) * NB * NACT) : nullptr;
        sample_kernel<<<NB, 256>>>(u_noise + (size_t)t * NB * 1024, out + (size_t)t * NB,
                                   bp2, bo2, an);
    }
}

// round 16
// speedup vs baseline: 1.1278x; 1.1278x over previous
#include <cuda_runtime.h>
#include <math.h>

#define NB 256        // batch
#define NT 64         // timesteps
#define NACT 6
#define GDIM 3072
#define ZA_LD 1040    // 1024 z + 6 act + 10 zero pad (K=1040 multiple of 16)
#define WI1_K 1040

// ---------------- scratch (device globals: no allocation allowed) ----------------
__device__ float g_ZA[NB * ZA_LD];        // [z0 (1024) | action (6) | pad] (t=0 dense only)
__device__ float g_H1[NB * 1024];         // imagine hidden (post-silu)
__device__ float g_IB[NB * 2048];         // [inp (1024) | belief (1024)]
__device__ float g_HP[NB * 1024];         // prior hidden (post-silu)
__device__ float g_HO[NB * 1024];         // post hidden (post-silu)
__device__ float g_PP[8][NB * 1024];      // split-K partial pool (reused per phase)
__device__ float g_GG[4][NB * GDIM];      // gg GEMM partials
__device__ float g_Wi1p[WI1_K * 1024];    // Wi1 zero-padded to K=1040 rows (t=0 dense)
__device__ int   g_zidx[NB * 32];         // per (row, stoch): global k of the one-hot
__device__ float g_zval[NB * 32];         // its value ((1+qp)-qp)

// ---------------- helpers ----------------
__device__ __forceinline__ float warp_sum(float v) {
#pragma unroll
    for (int o = 16; o; o >>= 1) v += __shfl_xor_sync(0xffffffffu, v, o);
    return v;
}
__device__ __forceinline__ float warp_max(float v) {
#pragma unroll
    for (int o = 16; o; o >>= 1) v = fmaxf(v, __shfl_xor_sync(0xffffffffu, v, o));
    return v;
}
__device__ __forceinline__ float silu_f(float x) {
    double e = exp(-(double)x);
    return (float)((double)x / (1.0 + e));
}
__device__ __forceinline__ float sigmoid_f(float x) {
    return (float)(1.0 / (1.0 + exp(-(double)x)));
}

__device__ __forceinline__ void cp16(void* smem, const void* g) {
    unsigned s = (unsigned)__cvta_generic_to_shared(smem);
    asm volatile("cp.async.ca.shared.global [%0], [%1], 16;\n" :: "r"(s), "l"(g));
}
__device__ __forceinline__ void cp_commit() { asm volatile("cp.async.commit_group;\n"); }
__device__ __forceinline__ void cp_wait0()  { asm volatile("cp.async.wait_group 0;\n"); }

// ---------------- init ----------------
__global__ void init_kernel(const float* __restrict__ z0, const float* __restrict__ b0,
                            const float* __restrict__ actions0) {
    int i = blockIdx.x * blockDim.x + threadIdx.x;
    if (i < NB * 1024) {
        int r = i >> 10, c = i & 1023;
        g_ZA[r * ZA_LD + c] = z0[i];
        g_IB[r * 2048 + 1024 + c] = b0[i];
        if (c >= 1024 - 10) g_ZA[r * ZA_LD + (c + 16)] = 0.0f;  // cols 1030..1039
        if (c < NACT) g_ZA[r * ZA_LD + 1024 + c] = actions0[r * NACT + c];
    }
}
__global__ void padw_kernel(const float* __restrict__ Wi1) {
    int i = blockIdx.x * blockDim.x + threadIdx.x;
    if (i < WI1_K * 1024) {
        int r = i >> 10;
        g_Wi1p[i] = (r < 1030) ? Wi1[i] : 0.0f;
    }
}

// ---------------- GEMM problem descriptor: z-slice -> k-range ----------------
struct GP {
    const float* A;   int lda;    // k in [0, ksplit)
    const float* A2;  int lda2;   // k in [ksplit, K)
    int ksplit;
    const float* W;   int ldw;
    float* C;         int ldc;
    long long cstride;            // elements between split partial buffers
    int zlo;                      // first z owned by this problem
    int kfe;                      // end of first slice
    int kstep;                    // size of subsequent slices
};

// C_partial = A[k0:k1] @ W[k0:k1]. BM=BN=64, BK=16, 256 threads, 4x4 microtile,
// double-buffered, cp.async for W. blockIdx.z picks problem (zlo) + k-slice.
__global__ void __launch_bounds__(256) gemm10_kernel(GP p0, GP p1) {
    GP p = (blockIdx.z >= (unsigned)p1.zlo) ? p1 : p0;
    const int s = blockIdx.z - p.zlo;
    const int k0 = (s == 0) ? 0 : p.kfe + (s - 1) * p.kstep;
    const int k1 = p.kfe + s * p.kstep;
    float* Cout = p.C + (long long)s * p.cstride;

    __shared__ float As[2][16][64];
    __shared__ float Bs[2][16][64];

    const int tid = threadIdx.x;
    const int m0 = blockIdx.y * 64, n0 = blockIdx.x * 64;
    const int ar = tid & 63, ac = (tid >> 6) << 2;
    const int br = tid >> 4, bc = (tid & 15) << 2;
    const int ty = tid >> 4, tx = tid & 15;

    const int t0 = k0 >> 4, tN = k1 >> 4;

    auto aptr = [&](int t) -> const float* {
        int kb = t << 4;
        return (kb < p.ksplit)
            ? p.A  + (size_t)(m0 + ar) * p.lda  + kb + ac
            : p.A2 + (size_t)(m0 + ar) * p.lda2 + (kb - p.ksplit) + ac;
    };

    float acc[4][4] = {};
    {
        float4 a = *(const float4*)aptr(t0);
        cp16(&Bs[0][br][bc], p.W + (size_t)(k0 + br) * p.ldw + n0 + bc);
        cp_commit();
        As[0][ac + 0][ar] = a.x; As[0][ac + 1][ar] = a.y;
        As[0][ac + 2][ar] = a.z; As[0][ac + 3][ar] = a.w;
        cp_wait0();
    }
    __syncthreads();

    for (int t = t0; t < tN; t++) {
        const int cur = (t - t0) & 1, nxt = cur ^ 1;
        const bool more = (t + 1) < tN;
        float4 apf;
        if (more) {
            apf = *(const float4*)aptr(t + 1);
            cp16(&Bs[nxt][br][bc], p.W + (size_t)((t + 1) * 16 + br) * p.ldw + n0 + bc);
            cp_commit();
        }
#pragma unroll
        for (int kk = 0; kk < 16; kk++) {
            float4 a = *(const float4*)&As[cur][kk][ty * 4];
            float4 b = *(const float4*)&Bs[cur][kk][tx * 4];
            acc[0][0] += a.x * b.x; acc[0][1] += a.x * b.y; acc[0][2] += a.x * b.z; acc[0][3] += a.x * b.w;
            acc[1][0] += a.y * b.x; acc[1][1] += a.y * b.y; acc[1][2] += a.y * b.z; acc[1][3] += a.y * b.w;
            acc[2][0] += a.z * b.x; acc[2][1] += a.z * b.y; acc[2][2] += a.z * b.z; acc[2][3] += a.z * b.w;
            acc[3][0] += a.w * b.x; acc[3][1] += a.w * b.y; acc[3][2] += a.w * b.z; acc[3][3] += a.w * b.w;
        }
        if (more) {
            As[nxt][ac + 0][ar] = apf.x; As[nxt][ac + 1][ar] = apf.y;
            As[nxt][ac + 2][ar] = apf.z; As[nxt][ac + 3][ar] = apf.w;
            cp_wait0();
        }
        __syncthreads();
    }

#pragma unroll
    for (int i = 0; i < 4; i++) {
        const int m = m0 + ty * 4 + i;
        *(float4*)(Cout + (size_t)m * p.ldc + n0 + tx * 4) = *(float4*)&acc[i][0];
    }
}

// ---------------- sparse i1: H1 = silu(z_sparse @ Wi1 + a @ Wi1[1024:] + bi1) ----
// z has exactly one nonzero per 32-block (straight-through one-hot); 38 gathered
// weight rows per batch row. grid (16 col-tiles, 8 row-tiles), 256 threads.
// Each thread: one column, 8 interleaved row accumulators (MLP=8 L2 gathers).
__global__ void __launch_bounds__(256) sparse_i1_kernel(
    const float* __restrict__ actions_t, const float* __restrict__ Wi1,
    const float* __restrict__ bi1) {
    __shared__ int   sidx[32][32];
    __shared__ float sval[32][32];
    __shared__ float sact[32][NACT];

    const int tid = threadIdx.x;
    const int r0 = blockIdx.y * 32, c0 = blockIdx.x * 64;

    for (int i = tid; i < 32 * 32; i += 256) {
        int r = i >> 5, s = i & 31;
        sidx[r][s] = g_zidx[(r0 + r) * 32 + s];
        sval[r][s] = g_zval[(r0 + r) * 32 + s];
    }
    for (int i = tid; i < 32 * NACT; i += 256) {
        int r = i / NACT, c = i - r * NACT;
        sact[r][c] = actions_t[(r0 + r) * NACT + c];
    }
    __syncthreads();

    const int tx = tid & 63, ty = tid >> 6;   // column, row-group (8 rows each)
    const int col = c0 + tx;

    float acc[8];
#pragma unroll
    for (int j = 0; j < 8; j++) acc[j] = 0.0f;

    // 32 one-hot terms, ascending k (s-groups ascending; one k per group)
    for (int s = 0; s < 32; s++) {
#pragma unroll
        for (int j = 0; j < 8; j++) {
            int r = ty * 8 + j;
            acc[j] += sval[r][s] * __ldg(&Wi1[(size_t)sidx[r][s] * 1024 + col]);
        }
    }
    // action terms k = 1024..1029 (weight rows shared across all rows)
    float aw[NACT];
#pragma unroll
    for (int c = 0; c < NACT; c++) aw[c] = __ldg(&Wi1[(size_t)(1024 + c) * 1024 + col]);
#pragma unroll
    for (int j = 0; j < 8; j++) {
        int r = ty * 8 + j;
#pragma unroll
        for (int c = 0; c < NACT; c++) acc[j] += sact[r][c] * aw[c];
    }

    const float b = bi1[col];
#pragma unroll
    for (int j = 0; j < 8; j++) {
        int r = ty * 8 + j;
        g_H1[(size_t)(r0 + r) * 1024 + col] = silu_f(acc[j] + b);
    }
}

// ---------------- fuse8: out = [silu](sum PP[0..7] + bias) ----------------------
__global__ void fuse8_kernel(const float* __restrict__ bias, float* __restrict__ out,
                             int ldo, int dsilu) {
    int i = (blockIdx.x * blockDim.x + threadIdx.x) << 2;
    int r = i >> 10, c = i & 1023;
    float4 o = *(const float4*)&g_PP[0][i];
#pragma unroll
    for (int s = 1; s < 8; s++) {
        float4 v = *(const float4*)&g_PP[s][i];
        o.x += v.x; o.y += v.y; o.z += v.z; o.w += v.w;
    }
    float4 b4 = *(const float4*)&bias[c];
    o.x += b4.x; o.y += b4.y; o.z += b4.z; o.w += b4.w;
    if (dsilu) { o.x = silu_f(o.x); o.y = silu_f(o.y); o.z = silu_f(o.z); o.w = silu_f(o.w); }
    *(float4*)(out + (size_t)r * ldo + c) = o;
}

// ---------------- fuse44: HP = silu(PP[0..3]+bp1), HO = silu(PP[4..7]+bo1) -------
__global__ void fuse44_kernel(const float* __restrict__ bp1, const float* __restrict__ bo1) {
    int i = (blockIdx.x * blockDim.x + threadIdx.x) << 2;
    int c = i & 1023;
    const int base = blockIdx.y * 4;
    const float* bias = blockIdx.y ? bo1 : bp1;
    float* out = blockIdx.y ? g_HO : g_HP;
    float4 o = *(const float4*)&g_PP[base][i];
#pragma unroll
    for (int s = 1; s < 4; s++) {
        float4 v = *(const float4*)&g_PP[base + s][i];
        o.x += v.x; o.y += v.y; o.z += v.z; o.w += v.w;
    }
    float4 b4 = *(const float4*)&bias[c];
    o.x = silu_f(o.x + b4.x);
    o.y = silu_f(o.y + b4.y);
    o.z = silu_f(o.z + b4.z);
    o.w = silu_f(o.w + b4.w);
    *(float4*)(out + i) = o;
}

// ---------------- LayerNorm(3072, eps=1e-3) + GRU update (sums 4 GG partials) ----
__global__ void lngru_kernel(const float* __restrict__ ln_scale, const float* __restrict__ ln_bias) {
    const int row = blockIdx.x;
    const int tid = threadIdx.x;
    __shared__ float sh[8];
    __shared__ float bcast;

    const float* g0 = g_GG[0] + (size_t)row * GDIM;
    const float* g1 = g_GG[1] + (size_t)row * GDIM;
    const float* g2 = g_GG[2] + (size_t)row * GDIM;
    const float* g3 = g_GG[3] + (size_t)row * GDIM;
    float x[12];
    float s = 0.0f;
#pragma unroll
    for (int i = 0; i < 12; i++) {
        int j = tid + i * 256;
        x[i] = ((g0[j] + g1[j]) + (g2[j] + g3[j]));
        s += x[i];
    }

    s = warp_sum(s);
    if ((tid & 31) == 0) sh[tid >> 5] = s;
    __syncthreads();
    if (tid < 32) {
        float t = (tid < 8) ? sh[tid] : 0.0f;
        t = warp_sum(t);
        if (tid == 0) bcast = t;
    }
    __syncthreads();
    const float mu = __fdiv_rn(bcast, 3072.0f);
    __syncthreads();

    float v = 0.0f;
#pragma unroll
    for (int i = 0; i < 12; i++) { float d = x[i] - mu; v += d * d; }
    v = warp_sum(v);
    if ((tid & 31) == 0) sh[tid >> 5] = v;
    __syncthreads();
    if (tid < 32) {
        float t = (tid < 8) ? sh[tid] : 0.0f;
        t = warp_sum(t);
        if (tid == 0) bcast = t;
    }
    __syncthreads();
    const float var = __fdiv_rn(bcast, 3072.0f);
    const float denom = __fsqrt_rn(var + 1e-3f);

#pragma unroll
    for (int jj = 0; jj < 4; jj++) {
        int j = tid + jj * 256;
        float yr = __fdiv_rn(x[jj]     - mu, denom) * ln_scale[j]        + ln_bias[j];
        float yc = __fdiv_rn(x[jj + 4] - mu, denom) * ln_scale[j + 1024] + ln_bias[j + 1024];
        float yu = __fdiv_rn(x[jj + 8] - mu, denom) * ln_scale[j + 2048] + ln_bias[j + 2048];
        float reset = sigmoid_f(yr);
        float cand  = (float)tanh((double)(reset * yc));
        float upd   = sigmoid_f(yu - 1.0f);   // UPDATE_BIAS = -1
        float bprev = g_IB[(size_t)row * 2048 + 1024 + j];
        float bn = upd * cand + (1.0f - upd) * bprev;
        g_IB[(size_t)row * 2048 + 1024 + j] = bn;
    }
}

// ---------------- softmax/unimix/KL + gumbel sample -> (zidx, zval) --------------
__global__ void sample_kernel(const float* __restrict__ U_t, float* __restrict__ losses_t,
                              const float* __restrict__ bp2, const float* __restrict__ bo2) {
    const int row = blockIdx.x;
    const int tid = threadIdx.x;
    const int warp = tid >> 5, lane = tid & 31;
    __shared__ float klsh[8];

    float klacc = 0.0f;
#pragma unroll
    for (int sg = 0; sg < 4; sg++) {
        const int s2 = warp * 4 + sg;
        const int col = s2 * 32 + lane;
        const int idx = row * 1024 + col;

        float pl = ((g_PP[0][idx] + g_PP[1][idx]) + (g_PP[2][idx] + g_PP[3][idx])) + bp2[col];
        float ql = ((g_PP[4][idx] + g_PP[5][idx]) + (g_PP[6][idx] + g_PP[7][idx])) + bo2[col];
        pl = fminf(fmaxf(pl, -20.0f), 20.0f);
        ql = fminf(fmaxf(ql, -20.0f), 20.0f);

        float pm = warp_max(pl);
        float pe = (float)exp((double)(pl - pm));
        float ps = warp_sum(pe);
        float pp = __fdiv_rn(pe, ps) * 0.99f + (0.01f / 32.0f);

        float qm = warp_max(ql);
        float qe = (float)exp((double)(ql - qm));
        float qs = warp_sum(qe);
        float qp = __fdiv_rn(qe, qs) * 0.99f + (0.01f / 32.0f);

        klacc += qp * (float)(log((double)(qp + 1e-8f)) - log((double)(pp + 1e-8f)));

        float u = U_t[idx];
        float gum = (float)(-log(-log((double)u + 1e-6) + 1e-6));
        float val = (float)log((double)fmaxf(qp, 1e-6f)) + gum;
        float bv = val; int bi = lane;
#pragma unroll
        for (int o = 16; o; o >>= 1) {
            float ov = __shfl_xor_sync(0xffffffffu, bv, o);
            int   oi = __shfl_xor_sync(0xffffffffu, bi, o);
            if (ov > bv || (ov == bv && oi < bi)) { bv = ov; bi = oi; }
        }
        // straight-through value at the argmax lane; all other entries are exact 0
        if (lane == bi) {
            float z = __fsub_rn(__fadd_rn(1.0f, qp), qp);
            g_zidx[row * 32 + s2] = col;        // global k of the nonzero
            g_zval[row * 32 + s2] = z;
        }
    }

    float w = warp_sum(klacc);
    if (lane == 0) klsh[warp] = w;
    __syncthreads();
    if (tid == 0) {
        float kl = 0.0f;
#pragma unroll
        for (int i = 0; i < 8; i++) kl += klsh[i];
        float m = fmaxf(kl, 0.1f);
        losses_t[row] = 1.0f * m + 0.1f * m;
    }
}

// ---------------- launch ----------------
extern "C" void kernel_launch(void* const* d_in, const int* in_sizes, int n_in,
                              void* d_out, int out_size) {
    const float* b0       = (const float*)d_in[0];
    const float* z0       = (const float*)d_in[1];
    const float* actions  = (const float*)d_in[2];
    const float* obs      = (const float*)d_in[3];
    const float* u_noise  = (const float*)d_in[4];
    const float* Wi1      = (const float*)d_in[5];
    const float* bi1      = (const float*)d_in[6];
    const float* Wi2      = (const float*)d_in[7];
    const float* bi2      = (const float*)d_in[8];
    const float* Wg       = (const float*)d_in[9];
    const float* ln_scale = (const float*)d_in[10];
    const float* ln_bias  = (const float*)d_in[11];
    const float* Wo1      = (const float*)d_in[12];
    const float* bo1      = (const float*)d_in[13];
    const float* Wo2      = (const float*)d_in[14];
    const float* bo2      = (const float*)d_in[15];
    const float* Wp1      = (const float*)d_in[16];
    const float* bp1      = (const float*)d_in[17];
    const float* Wp2      = (const float*)d_in[18];
    const float* bp2      = (const float*)d_in[19];
    float* out = (float*)d_out;

    float *pZA, *pH1, *pIB, *pHP, *pHO, *pWi1p, *pPP;
    cudaGetSymbolAddress((void**)&pZA, g_ZA);
    cudaGetSymbolAddress((void**)&pH1, g_H1);
    cudaGetSymbolAddress((void**)&pIB, g_IB);
    cudaGetSymbolAddress((void**)&pHP, g_HP);
    cudaGetSymbolAddress((void**)&pHO, g_HO);
    cudaGetSymbolAddress((void**)&pWi1p, g_Wi1p);
    cudaGetSymbolAddress((void**)&pPP, g_PP);
    float* pGG;
    cudaGetSymbolAddress((void**)&pGG, g_GG);

    const long long PSTRIDE = (long long)NB * 1024;
    const long long GSTRIDE = (long long)NB * GDIM;
    const float* belief = pIB + 1024;

    init_kernel<<<(NB * 1024 + 255) / 256, 256>>>(z0, b0, actions);
    padw_kernel<<<(WI1_K * 1024 + 255) / 256, 256>>>(Wi1);

    const dim3 gS8(16, 4, 8);   // N=1024, 8 z-slices: 512 blocks
    const dim3 gG4(48, 4, 4);   // N=3072, split-4: 768 blocks
    const dim3 gSP(16, 8, 1);   // sparse i1: 128 blocks
    const dim3 gF(256, 1, 1);
    const dim3 gF2(256, 2, 1);

    for (int t = 0; t < NT; t++) {
        const float* obs_t = obs + (size_t)t * NB * 1024;

        // ---- imagine layer 1 ----
        if (t == 0) {
            // dense: z0 is random uniform, not one-hot
            GP a{pZA, ZA_LD, pZA, ZA_LD, WI1_K, pWi1p, 1024, pPP, 1024, PSTRIDE, 0, 144, 128};
            gemm10_kernel<<<gS8, 256>>>(a, a);
            fuse8_kernel<<<gF, 256>>>(bi1, pH1, 1024, 1);
        } else {
            // sparse: one-hot z (38 gathered rows per batch row) + fused bias/silu
            sparse_i1_kernel<<<gSP, 256>>>(actions + (size_t)t * NB * NACT, Wi1, bi1);
        }

        // ---- imagine layer 2: H1 @ Wi2, K=1024, split-8 ----
        {
            GP a{pH1, 1024, pH1, 1024, 1024, Wi2, 1024, pPP, 1024, PSTRIDE, 0, 128, 128};
            gemm10_kernel<<<gS8, 256>>>(a, a);
        }
        fuse8_kernel<<<gF, 256>>>(bi2, pIB, 2048, 0);

        // ---- GRU gates: IB @ Wg, K=2048, N=3072, split-4 ----
        {
            GP a{pIB, 2048, pIB, 2048, 2048, Wg, 3072, pGG, 3072, GSTRIDE, 0, 512, 512};
            gemm10_kernel<<<gG4, 256>>>(a, a);
        }
        lngru_kernel<<<NB, 256>>>(ln_scale, ln_bias);

        // ---- prior L1 split-4 (z 0..3) || posterior L1 split-4 (z 4..7) ----
        {
            GP a{belief, 2048, belief, 2048, 1024, Wp1, 1024, pPP, 1024, PSTRIDE, 0, 256, 256};
            GP b{obs_t,  1024, belief, 2048, 1024, Wo1, 1024, pPP + 4 * PSTRIDE, 1024, PSTRIDE, 4, 512, 512};
            gemm10_kernel<<<gS8, 256>>>(a, b);
        }
        fuse44_kernel<<<gF2, 256>>>(bp1, bo1);

        // ---- prior L2 split-4 || posterior L2 split-4 ----
        {
            GP a{pHP, 1024, pHP, 1024, 1024, Wp2, 1024, pPP, 1024, PSTRIDE, 0, 256, 256};
            GP b{pHO, 1024, pHO, 1024, 1024, Wo2, 1024, pPP + 4 * PSTRIDE, 1024, PSTRIDE, 4, 256, 256};
            gemm10_kernel<<<gS8, 256>>>(a, b);
        }

        // ---- probs + KL + gumbel sample -> (zidx, zval) for next step ----
        sample_kernel<<<NB, 256>>>(u_noise + (size_t)t * NB * 1024, out + (size_t)t * NB,
                                   bp2, bo2);
    }
}